// round 16
// baseline (speedup 1.0000x reference)
#include <cuda_runtime.h>
#include <cuda_bf16.h>
#include <cuda_fp16.h>
#include <cstdint>

#define Bn 32
#define Nn 577
#define Cn 768
#define Hn 12
#define Dn 64
#define Mn (Bn*Nn)          // 18464
#define QKV_N (3*Cn)        // 2304
#define BHD ((size_t)Bn*Hn*Nn*Dn)   // 14,180,352

// Scratch (__device__ globals)
__device__ __align__(16) __half g_xh[(size_t)Mn*Cn];                         // x fp16
__device__ __align__(16) __half g_wq[(size_t)QKV_N*Cn];                      // w_qkv fp16
__device__ __align__(16) __half g_wp[(size_t)Cn*Cn];                         // w_proj fp16
__device__ __align__(16) __half g_qh[BHD], g_ql[BHD];                        // Q fp16 hi/lo
__device__ __align__(16) __half g_k[BHD], g_v[BHD];                          // K,V fp16
__device__ __align__(16) __half g_aoh[(size_t)Mn*Cn];                        // AO fp16

// ---------------------------------------------------------------------------
// helpers
// ---------------------------------------------------------------------------
__device__ __forceinline__ uint32_t smem_u32(const void* p){
    uint32_t a;
    asm("{ .reg .u64 t; cvta.to.shared.u64 t, %1; cvt.u32.u64 %0, t; }"
        : "=r"(a) : "l"(p));
    return a;
}
__device__ __forceinline__ void ldsm4(uint32_t (&r)[4], uint32_t a){
    asm volatile("ldmatrix.sync.aligned.m8n8.x4.shared.b16 {%0,%1,%2,%3}, [%4];"
        : "=r"(r[0]),"=r"(r[1]),"=r"(r[2]),"=r"(r[3]) : "r"(a));
}
__device__ __forceinline__ void ldsm4t(uint32_t (&r)[4], uint32_t a){
    asm volatile("ldmatrix.sync.aligned.m8n8.x4.trans.shared.b16 {%0,%1,%2,%3}, [%4];"
        : "=r"(r[0]),"=r"(r[1]),"=r"(r[2]),"=r"(r[3]) : "r"(a));
}
__device__ __forceinline__ void mma16816h(float* c, const uint32_t* a,
                                          uint32_t b0, uint32_t b1){
    asm volatile("mma.sync.aligned.m16n8k16.row.col.f32.f16.f16.f32 "
        "{%0,%1,%2,%3}, {%4,%5,%6,%7}, {%8,%9}, {%0,%1,%2,%3};"
        : "+f"(c[0]),"+f"(c[1]),"+f"(c[2]),"+f"(c[3])
        : "r"(a[0]),"r"(a[1]),"r"(a[2]),"r"(a[3]), "r"(b0),"r"(b1));
}
__device__ __forceinline__ void cpa(uint32_t s, const void* g, uint32_t n){
    asm volatile("cp.async.cg.shared.global [%0], [%1], 16, %2;"
                 :: "r"(s), "l"(g), "r"(n) : "memory");
}
__device__ __forceinline__ uint32_t packh(float x, float y){
    __half2 t = __floats2half2_rn(x, y);
    return *reinterpret_cast<uint32_t*>(&t);
}

// ---------------------------------------------------------------------------
// merged conversion kernel: x, w_qkv, w_proj -> fp16
// ---------------------------------------------------------------------------
#define NBX ((Mn*Cn)/1024)        // 13848
#define NBQ ((QKV_N*Cn)/1024)     // 1728
#define NBP ((Cn*Cn)/1024)        // 576

__global__ __launch_bounds__(256) void conv_all(
    const float* __restrict__ x, const float* __restrict__ wq,
    const float* __restrict__ wp,
    __half* __restrict__ xh,
    __half* __restrict__ wqd, __half* __restrict__ wpd)
{
    const int b = blockIdx.x;
    const int t4 = threadIdx.x * 4;
    const float* src; __half* dst; int i;
    if (b < NBX){       src = x;  dst = xh;  i = b*1024 + t4; }
    else if (b < NBX+NBQ){ src = wq; dst = wqd; i = (b-NBX)*1024 + t4; }
    else {              src = wp; dst = wpd; i = (b-NBX-NBQ)*1024 + t4; }
    float4 v = *(const float4*)(src + i);
    *(uint2*)(dst + i) = make_uint2(packh(v.x, v.y), packh(v.z, v.w));
}

// ---------------------------------------------------------------------------
// fp16 GEMM (1 A-term x single-fp16 B), k-stage 64, 3-deep pipe, 2 CTAs/SM.
// EPI==0: RoPE + q-scale(log2e folded) -> fp16 q hi/lo, k/v single, [B,H,N,D]
//         via smem staging + coalesced 16B row stores (sec constant per CTA).
// EPI==1: +bias -> fp32 Out
// ---------------------------------------------------------------------------
#define KS2 64
#define NSTG2 (Cn/KS2)        // 12
#define TILE16K 16384
#define SMEM_GM 98304         // 96KB -> 2 CTAs/SM

#define SWZ128(row_, grp_) ((uint32_t)(row_)*128u + ((((uint32_t)(grp_)) ^ ((uint32_t)(row_)&7u))<<4))

template<int EPI>
__global__ __launch_bounds__(256,2) void gemm_h1(
    const __half* __restrict__ Ah, const __half* __restrict__ Bh,
    const float* __restrict__ cosb, const float* __restrict__ sinb,
    const float* __restrict__ bias, float* __restrict__ Out)
{
    extern __shared__ char sm[];
    const uint32_t smb = smem_u32(sm);
    constexpr int STG_B = 2*TILE16K;   // 32KB : A|B
    constexpr int DEPTH = 3;

    const int tid  = threadIdx.x;
    const int wid  = tid >> 5;
    const int lane = tid & 31;
    const int m0 = blockIdx.y * 128;
    const int n0 = blockIdx.x * 128;
    const int wm = wid & 3;
    const int wn = wid >> 2;

    float acc[2][8][4];
#pragma unroll
    for (int im=0;im<2;im++)
#pragma unroll
        for (int j=0;j<8;j++)
#pragma unroll
            for (int q=0;q<4;q++) acc[im][j][q] = 0.f;

#define GISSUE(s_, b_) do{ \
    const uint32_t bb_ = smb + (uint32_t)(b_)*STG_B; \
    const int kt_ = (s_)*KS2; \
    _Pragma("unroll") \
    for (int r_ = 0; r_ < 4; r_++){ \
        const int idx_ = tid + r_*256; \
        const uint32_t row_ = (uint32_t)(idx_ >> 3); \
        const uint32_t grp_ = (uint32_t)(idx_ & 7); \
        const uint32_t dst_ = bb_ + SWZ128(row_, grp_); \
        const uint32_t an_  = ((int)(m0 + row_) < Mn) ? 16u : 0u; \
        cpa(dst_,           Ah + (size_t)(m0 + row_)*Cn + kt_ + grp_*8, an_); \
        cpa(dst_ + TILE16K, Bh + (size_t)(n0 + row_)*Cn + kt_ + grp_*8, 16u); \
    } \
    asm volatile("cp.async.commit_group;":::"memory"); \
}while(0)

    GISSUE(0, 0);
    GISSUE(1, 1);
    GISSUE(2, 2);

    const uint32_t ar0 = (uint32_t)(wm*32 + (lane & 15));
    const uint32_t ar1 = ar0 + 16;
    const uint32_t brb = (uint32_t)(wn*64 + (lane & 7) + ((lane >> 4) << 3));

    for (int s = 0; s < NSTG2; s++){
        if (s + 2 < NSTG2)      asm volatile("cp.async.wait_group 2;":::"memory");
        else if (s + 1 < NSTG2) asm volatile("cp.async.wait_group 1;":::"memory");
        else                    asm volatile("cp.async.wait_group 0;":::"memory");
        __syncthreads();

        const uint32_t sb = smb + (uint32_t)(s % DEPTH)*STG_B;
#pragma unroll
        for (int kk = 0; kk < 4; kk++){
            const uint32_t gA = (uint32_t)(kk*2 + (lane >> 4));
            const uint32_t gB = (uint32_t)(kk*2 + ((lane >> 3) & 1));
            uint32_t ah[2][4], bhf[4][4];
            ldsm4(ah[0], sb + SWZ128(ar0, gA));
            ldsm4(ah[1], sb + SWZ128(ar1, gA));
#pragma unroll
            for (int t2 = 0; t2 < 4; t2++){
                const uint32_t br = brb + (uint32_t)(t2*16);
                ldsm4(bhf[t2], sb + TILE16K + SWZ128(br, gB));
            }
#pragma unroll
            for (int im = 0; im < 2; im++)
#pragma unroll
                for (int j = 0; j < 8; j++)
                    mma16816h(acc[im][j], ah[im],
                              bhf[j>>1][(j&1)*2], bhf[j>>1][(j&1)*2+1]);
        }
        __syncthreads();
        if (s + DEPTH < NSTG2) GISSUE(s + DEPTH, s % DEPTH);
    }
#undef GISSUE

    if (EPI == 0){
        // sec is constant for the whole CTA (tile never straddles q/k/v)
        const int sec  = n0 / Cn;
        const int rem0 = n0 - sec*Cn;          // head-base*64 within section
        const float QSCALE = 0.125f * 1.44269504088896f;
        // staging: hi at rows [0,128), lo at +128 rows (q only). pitch 136 halfwords.
        __half* Dh = (__half*)sm;
        __half* Dl = Dh + 128*136;
        int bb4[2][2], n4[2][2];
#pragma unroll
        for (int im = 0; im < 2; im++)
#pragma unroll
            for (int rr = 0; rr < 2; rr++){
                const int m = m0 + wm*32 + im*16 + (lane>>2) + rr*8;
                const int bb = (m < Mn) ? (m / Nn) : 0;
                bb4[im][rr] = bb;
                n4[im][rr]  = m - bb*Nn;
            }
#pragma unroll
        for (int im = 0; im < 2; im++){
#pragma unroll
            for (int j = 0; j < 8; j++){
                const int cl = wn*64 + j*8 + (lane&3)*2;
                const int d  = (rem0 + cl) & 63;
#pragma unroll
                for (int rr = 0; rr < 2; rr++){
                    const int r = wm*32 + im*16 + (lane>>2) + rr*8;
                    float v1 = acc[im][j][rr*2+0];
                    float v2 = acc[im][j][rr*2+1];
                    const int n = n4[im][rr];
                    if (sec < 2 && n > 0){
                        const float cs = cosb[(n-1)*(Dn/2) + (d>>1)];
                        const float sn = sinb[(n-1)*(Dn/2) + (d>>1)];
                        const float r1 = v1*cs - v2*sn;
                        const float r2 = v1*sn + v2*cs;
                        v1 = r1; v2 = r2;
                    }
                    if (sec == 0){
                        v1 *= QSCALE; v2 *= QSCALE;
                        const __half h1 = __float2half_rn(v1), h2 = __float2half_rn(v2);
                        uint32_t hp; { __half2 t; t.x=h1; t.y=h2;
                                       hp=*reinterpret_cast<uint32_t*>(&t); }
                        *reinterpret_cast<uint32_t*>(Dh + r*136 + cl) = hp;
                        *reinterpret_cast<uint32_t*>(Dl + r*136 + cl) =
                            packh(v1 - __half2float(h1), v2 - __half2float(h2));
                    } else {
                        *reinterpret_cast<uint32_t*>(Dh + r*136 + cl) = packh(v1, v2);
                    }
                }
            }
        }
        __syncthreads();
        // coalesced writers: 2 threads per row, 128B per thread per tensor row
        {
            const int row  = tid >> 1;
            const int half = tid & 1;
            const int m = m0 + row;
            if (m < Mn){
                const int bb = m / Nn;
                const int n  = m - bb*Nn;
                const int hh = (rem0 >> 6) + half;
                const size_t dst = ((size_t)(bb*Hn + hh)*Nn + n)*Dn;
                const __half* srh = Dh + row*136 + half*64;
                __half* gh = (sec == 0) ? g_qh : (sec == 1) ? g_k : g_v;
#pragma unroll
                for (int j = 0; j < 64; j += 8)
                    *(uint4*)(gh + dst + j) = *(const uint4*)(srh + j);
                if (sec == 0){
                    const __half* srl = Dl + row*136 + half*64;
#pragma unroll
                    for (int j = 0; j < 64; j += 8)
                        *(uint4*)(g_ql + dst + j) = *(const uint4*)(srl + j);
                }
            }
        }
    } else {
        float* Ds = (float*)sm;
#pragma unroll
        for (int im = 0; im < 2; im++){
#pragma unroll
            for (int j = 0; j < 8; j++){
                const int cl = wn*64 + j*8 + (lane&3)*2;
#pragma unroll
                for (int rr = 0; rr < 2; rr++){
                    const int r = wm*32 + im*16 + (lane>>2) + rr*8;
                    float v1 = acc[im][j][rr*2+0];
                    float v2 = acc[im][j][rr*2+1];
                    const int gc = n0 + cl;
                    v1 += bias[gc]; v2 += bias[gc+1];
                    Ds[r*132 + cl]   = v1;
                    Ds[r*132 + cl+1] = v2;
                }
            }
        }
        __syncthreads();
        const int row  = tid >> 1;
        const int half = tid & 1;
        const int m = m0 + row;
        if (m < Mn){
            float* dst = Out + (size_t)m*Cn + n0 + half*64;
            const float* src = &Ds[row*132 + half*64];
#pragma unroll
            for (int j = 0; j < 64; j += 4)
                *(float4*)&dst[j] = *(const float4*)&src[j];
        }
    }
}

// ---------------------------------------------------------------------------
// HMMA flash attention: S=(Qh+Ql)K, O+=P·V. exp2 softmax. 3-deep KV ring.
// Warps with no valid q-rows skip compute (barriers/issue unguarded).
// ---------------------------------------------------------------------------
#define AT_PITCH 144
#define AT_TILE  (64*AT_PITCH)        // 9216
#define KV_STAGE (2*AT_TILE)          // 18432 : K | V
#define AT_SMEM  (36864 + 3*KV_STAGE) // 92160
#define NTkv ((Nn+63)/64)             // 10

__global__ __launch_bounds__(256,2) void attn_tc()
{
    extern __shared__ char sm[];
    const uint32_t smb = smem_u32(sm);
    const int tid  = threadIdx.x;
    const int wid  = tid >> 5;
    const int lane = tid & 31;
    const int qt   = blockIdx.x;
    const int bh   = blockIdx.y;
    const int bb   = bh / Hn;
    const int h    = bh - bb*Hn;
    const bool wactive = (qt*128 + wid*16) < Nn;

    const __half* Qh = g_qh + (size_t)bh*Nn*Dn;
    const __half* Ql = g_ql + (size_t)bh*Nn*Dn;
    const __half* Kp = g_k  + (size_t)bh*Nn*Dn;
    const __half* Vp = g_v  + (size_t)bh*Nn*Dn;

    {
#pragma unroll
        for (int i = 0; i < 4; i++){
            const int idx = tid + i*256;
            const int r   = idx >> 3;
            const int j   = idx & 7;
            const int gr  = qt*128 + r;
            uint4 vh = make_uint4(0,0,0,0), vl = vh;
            if (gr < Nn){
                vh = *(const uint4*)(Qh + (size_t)gr*Dn + j*8);
                vl = *(const uint4*)(Ql + (size_t)gr*Dn + j*8);
            }
            *(uint4*)(sm + r*AT_PITCH + j*16)         = vh;
            *(uint4*)(sm + 18432 + r*AT_PITCH + j*16) = vl;
        }
    }

#define ISSUE_KV(t_, buf_) do{ \
    const int kv0 = (t_)*64; \
    const uint32_t bp = smb + 36864u + (uint32_t)(buf_)*KV_STAGE; \
    _Pragma("unroll") \
    for (int i_ = 0; i_ < 4; i_++){ \
        const int idx = tid + i_*256; \
        const int ts  = idx >> 9; \
        const int rem = idx & 511; \
        const int r_  = rem >> 3; \
        const int j_  = rem & 7; \
        const int gr  = kv0 + r_; \
        const __half* src = ts ? Vp : Kp; \
        const uint32_t n_ = (gr < Nn) ? 16u : 0u; \
        cpa(bp + (uint32_t)ts*AT_TILE + (uint32_t)(r_*AT_PITCH + j_*16), \
            src + (size_t)gr*Dn + j_*8, n_); \
    } \
    asm volatile("cp.async.commit_group;":::"memory"); \
}while(0)

    ISSUE_KV(0, 0);
    ISSUE_KV(1, 1);

    __syncthreads();
    uint32_t qfh[4][4], qfl[4][4];
    if (wactive){
        const uint32_t qa = smb + (uint32_t)((wid*16 + (lane&15))*AT_PITCH + (lane>>4)*16);
#pragma unroll
        for (int kk = 0; kk < 4; kk++){
            ldsm4(qfh[kk], qa + kk*32);
            ldsm4(qfl[kk], qa + 18432 + kk*32);
        }
    }

    float m0r = -1e30f, m1r = -1e30f, l0r = 0.f, l1r = 0.f;
    float o[8][4];
#pragma unroll
    for (int j=0;j<8;j++)
#pragma unroll
        for (int q=0;q<4;q++) o[j][q] = 0.f;

    int buf = 0;
    for (int t = 0; t < NTkv; t++){
        if (t < NTkv-1) asm volatile("cp.async.wait_group 1;":::"memory");
        else            asm volatile("cp.async.wait_group 0;":::"memory");
        __syncthreads();

        const uint32_t sb = smb + 36864u + (uint32_t)buf*KV_STAGE;

        if (wactive){
            float s[8][4];
#pragma unroll
            for (int j=0;j<8;j++)
#pragma unroll
                for (int q=0;q<4;q++) s[j][q] = 0.f;

#pragma unroll
            for (int kk = 0; kk < 4; kk++){
                uint32_t kh[4][4];
#pragma unroll
                for (int g = 0; g < 4; g++){
                    const uint32_t ka = sb
                        + (uint32_t)((g*16 + (lane&7) + ((lane>>4)<<3))*AT_PITCH
                                     + ((lane>>3)&1)*16 + kk*32);
                    ldsm4(kh[g], ka);
                }
#pragma unroll
                for (int j = 0; j < 8; j++)
                    mma16816h(s[j], qfh[kk], kh[j>>1][(j&1)*2], kh[j>>1][(j&1)*2+1]);
#pragma unroll
                for (int j = 0; j < 8; j++)
                    mma16816h(s[j], qfl[kk], kh[j>>1][(j&1)*2], kh[j>>1][(j&1)*2+1]);
            }

            if (t == NTkv-1){
#pragma unroll
                for (int j = 0; j < 8; j++){
                    const int c0 = t*64 + j*8 + (lane&3)*2;
                    if (c0   >= Nn){ s[j][0] = -1e30f; s[j][2] = -1e30f; }
                    if (c0+1 >= Nn){ s[j][1] = -1e30f; s[j][3] = -1e30f; }
                }
            }
            float mx0 = -1e30f, mx1 = -1e30f;
#pragma unroll
            for (int j = 0; j < 8; j++){
                mx0 = fmaxf(mx0, fmaxf(s[j][0], s[j][1]));
                mx1 = fmaxf(mx1, fmaxf(s[j][2], s[j][3]));
            }
            mx0 = fmaxf(mx0, __shfl_xor_sync(0xffffffffu, mx0, 1));
            mx0 = fmaxf(mx0, __shfl_xor_sync(0xffffffffu, mx0, 2));
            mx1 = fmaxf(mx1, __shfl_xor_sync(0xffffffffu, mx1, 1));
            mx1 = fmaxf(mx1, __shfl_xor_sync(0xffffffffu, mx1, 2));
            const float mn0 = fmaxf(m0r, mx0), mn1 = fmaxf(m1r, mx1);
            const float al0 = exp2f(m0r - mn0), al1 = exp2f(m1r - mn1);
            float rs0 = 0.f, rs1 = 0.f;
#pragma unroll
            for (int j = 0; j < 8; j++){
                s[j][0] = exp2f(s[j][0]-mn0); s[j][1] = exp2f(s[j][1]-mn0);
                s[j][2] = exp2f(s[j][2]-mn1); s[j][3] = exp2f(s[j][3]-mn1);
                rs0 += s[j][0] + s[j][1];
                rs1 += s[j][2] + s[j][3];
            }
            rs0 += __shfl_xor_sync(0xffffffffu, rs0, 1);
            rs0 += __shfl_xor_sync(0xffffffffu, rs0, 2);
            rs1 += __shfl_xor_sync(0xffffffffu, rs1, 1);
            rs1 += __shfl_xor_sync(0xffffffffu, rs1, 2);
            l0r = l0r*al0 + rs0;  m0r = mn0;
            l1r = l1r*al1 + rs1;  m1r = mn1;
#pragma unroll
            for (int j = 0; j < 8; j++){
                o[j][0] *= al0; o[j][1] *= al0;
                o[j][2] *= al1; o[j][3] *= al1;
            }

#pragma unroll
            for (int kk = 0; kk < 4; kk++){
                uint32_t pha[4];
                {
                    const int j0 = 2*kk, j1 = 2*kk+1;
                    pha[0] = packh(s[j0][0], s[j0][1]);
                    pha[1] = packh(s[j0][2], s[j0][3]);
                    pha[2] = packh(s[j1][0], s[j1][1]);
                    pha[3] = packh(s[j1][2], s[j1][3]);
                }
                uint32_t vh[4][4];
#pragma unroll
                for (int g = 0; g < 4; g++){
                    const uint32_t va = sb + AT_TILE
                        + (uint32_t)((kk*16 + (lane&7) + ((lane>>3)&1)*8)*AT_PITCH
                                     + ((lane>>4)*8 + g*16)*2);
                    ldsm4t(vh[g], va);
                }
#pragma unroll
                for (int j = 0; j < 8; j++)
                    mma16816h(o[j], pha, vh[j>>1][(j&1)*2], vh[j>>1][(j&1)*2+1]);
            }
        }

        if (t+2 < NTkv){
            const int nb = (t+2) % 3;
            ISSUE_KV(t+2, nb);
        }
        buf = (buf + 1 == 3) ? 0 : buf + 1;
    }
#undef ISSUE_KV

    if (wactive){
        const float inv0 = 1.f / l0r, inv1 = 1.f / l1r;
        const int r0 = qt*128 + wid*16 + (lane>>2);
        const int r1 = r0 + 8;
#pragma unroll
        for (int j = 0; j < 8; j++){
            const int col = h*Dn + j*8 + (lane&3)*2;
            if (r0 < Nn)
                *reinterpret_cast<uint32_t*>(g_aoh + (size_t)(bb*Nn + r0)*Cn + col)
                    = packh(o[j][0]*inv0, o[j][1]*inv0);
            if (r1 < Nn)
                *reinterpret_cast<uint32_t*>(g_aoh + (size_t)(bb*Nn + r1)*Cn + col)
                    = packh(o[j][2]*inv1, o[j][3]*inv1);
        }
    }
}

// ---------------------------------------------------------------------------
extern "C" void kernel_launch(void* const* d_in, const int* in_sizes, int n_in,
                              void* d_out, int out_size)
{
    (void)in_sizes; (void)n_in; (void)out_size;
    const float* x      = (const float*)d_in[0];
    const float* w_qkv  = (const float*)d_in[1];
    const float* w_proj = (const float*)d_in[2];
    const float* b_proj = (const float*)d_in[3];
    const float* cosb   = (const float*)d_in[4];
    const float* sinb   = (const float*)d_in[5];
    float* out = (float*)d_out;

    cudaFuncSetAttribute((const void*)gemm_h1<0>,
                         cudaFuncAttributeMaxDynamicSharedMemorySize, SMEM_GM);
    cudaFuncSetAttribute((const void*)gemm_h1<1>,
                         cudaFuncAttributeMaxDynamicSharedMemorySize, SMEM_GM);
    cudaFuncSetAttribute(attn_tc, cudaFuncAttributeMaxDynamicSharedMemorySize, AT_SMEM);

    __half *xh, *wq, *wp, *aoh;
    cudaGetSymbolAddress((void**)&xh,  g_xh);
    cudaGetSymbolAddress((void**)&wq,  g_wq);  cudaGetSymbolAddress((void**)&wp,  g_wp);
    cudaGetSymbolAddress((void**)&aoh, g_aoh);

    conv_all<<<NBX + NBQ + NBP, 256>>>(x, w_qkv, w_proj, xh, wq, wp);

    const int MT = (Mn + 127) / 128;   // 145
    gemm_h1<0><<<dim3(QKV_N/128, MT), 256, SMEM_GM>>>(xh, wq, cosb, sinb,
                                                      nullptr, nullptr);
    attn_tc<<<dim3((Nn+127)/128, Bn*Hn), 256, AT_SMEM>>>();
    gemm_h1<1><<<dim3(Cn/128, MT), 256, SMEM_GM>>>(aoh, wp, nullptr, nullptr,
                                                   b_proj, out);
}

// round 17
// speedup vs baseline: 1.0205x; 1.0205x over previous
#include <cuda_runtime.h>
#include <cuda_bf16.h>
#include <cuda_fp16.h>
#include <cstdint>

#define Bn 32
#define Nn 577
#define Cn 768
#define Hn 12
#define Dn 64
#define Mn (Bn*Nn)          // 18464
#define QKV_N (3*Cn)        // 2304
#define BHD ((size_t)Bn*Hn*Nn*Dn)   // 14,180,352

// Scratch (__device__ globals)
__device__ __align__(16) __half g_xh[(size_t)Mn*Cn];                         // x fp16
__device__ __align__(16) __half g_wq[(size_t)QKV_N*Cn];                      // w_qkv fp16
__device__ __align__(16) __half g_wp[(size_t)Cn*Cn];                         // w_proj fp16
__device__ __align__(16) __half g_qh[BHD], g_ql[BHD];                        // Q fp16 hi/lo
__device__ __align__(16) __half g_k[BHD], g_v[BHD];                          // K,V fp16
__device__ __align__(16) __half g_aoh[(size_t)Mn*Cn];                        // AO fp16

// ---------------------------------------------------------------------------
// helpers
// ---------------------------------------------------------------------------
__device__ __forceinline__ uint32_t smem_u32(const void* p){
    uint32_t a;
    asm("{ .reg .u64 t; cvta.to.shared.u64 t, %1; cvt.u32.u64 %0, t; }"
        : "=r"(a) : "l"(p));
    return a;
}
__device__ __forceinline__ void ldsm4(uint32_t (&r)[4], uint32_t a){
    asm volatile("ldmatrix.sync.aligned.m8n8.x4.shared.b16 {%0,%1,%2,%3}, [%4];"
        : "=r"(r[0]),"=r"(r[1]),"=r"(r[2]),"=r"(r[3]) : "r"(a));
}
__device__ __forceinline__ void ldsm4t(uint32_t (&r)[4], uint32_t a){
    asm volatile("ldmatrix.sync.aligned.m8n8.x4.trans.shared.b16 {%0,%1,%2,%3}, [%4];"
        : "=r"(r[0]),"=r"(r[1]),"=r"(r[2]),"=r"(r[3]) : "r"(a));
}
__device__ __forceinline__ void mma16816h(float* c, const uint32_t* a,
                                          uint32_t b0, uint32_t b1){
    asm volatile("mma.sync.aligned.m16n8k16.row.col.f32.f16.f16.f32 "
        "{%0,%1,%2,%3}, {%4,%5,%6,%7}, {%8,%9}, {%0,%1,%2,%3};"
        : "+f"(c[0]),"+f"(c[1]),"+f"(c[2]),"+f"(c[3])
        : "r"(a[0]),"r"(a[1]),"r"(a[2]),"r"(a[3]), "r"(b0),"r"(b1));
}
__device__ __forceinline__ void cpa(uint32_t s, const void* g, uint32_t n){
    asm volatile("cp.async.cg.shared.global [%0], [%1], 16, %2;"
                 :: "r"(s), "l"(g), "r"(n) : "memory");
}
__device__ __forceinline__ uint32_t packh(float x, float y){
    __half2 t = __floats2half2_rn(x, y);
    return *reinterpret_cast<uint32_t*>(&t);
}
__device__ __forceinline__ void store_pairh(__half* dh, __half* dl,
                                            size_t idx, float v1, float v2){
    const __half h1 = __float2half_rn(v1), h2 = __float2half_rn(v2);
    uint32_t hp; { __half2 t; t.x=h1; t.y=h2; hp=*reinterpret_cast<uint32_t*>(&t); }
    *reinterpret_cast<uint32_t*>(dh + idx) = hp;
    *reinterpret_cast<uint32_t*>(dl + idx) =
        packh(v1 - __half2float(h1), v2 - __half2float(h2));
}

// ---------------------------------------------------------------------------
// merged conversion kernel: x, w_qkv, w_proj -> fp16
// ---------------------------------------------------------------------------
#define NBX ((Mn*Cn)/1024)        // 13848
#define NBQ ((QKV_N*Cn)/1024)     // 1728
#define NBP ((Cn*Cn)/1024)        // 576

__global__ __launch_bounds__(256) void conv_all(
    const float* __restrict__ x, const float* __restrict__ wq,
    const float* __restrict__ wp,
    __half* __restrict__ xh,
    __half* __restrict__ wqd, __half* __restrict__ wpd)
{
    const int b = blockIdx.x;
    const int t4 = threadIdx.x * 4;
    const float* src; __half* dst; int i;
    if (b < NBX){       src = x;  dst = xh;  i = b*1024 + t4; }
    else if (b < NBX+NBQ){ src = wq; dst = wqd; i = (b-NBX)*1024 + t4; }
    else {              src = wp; dst = wpd; i = (b-NBX-NBQ)*1024 + t4; }
    float4 v = *(const float4*)(src + i);
    *(uint2*)(dst + i) = make_uint2(packh(v.x, v.y), packh(v.z, v.w));
}

// ---------------------------------------------------------------------------
// fp16 GEMM template: NT A-terms (1 or 2) x single-fp16 B.
// NT==1: 2 tiles/stage (32KB), 3-deep pipe.  NT==2: 3 tiles/stage, 2-deep.
// EPI==0: RoPE + q-scale(incl. log2e) -> fp16 q hi/lo, k/v single, [B,H,N,D]
// EPI==1: +bias -> fp32 Out
// ---------------------------------------------------------------------------
#define KS2 64
#define NSTG2 (Cn/KS2)        // 12
#define TILE16K 16384
#define SMEM_GM 98304         // 96KB -> 2 CTAs/SM

#define SWZ128(row_, grp_) ((uint32_t)(row_)*128u + ((((uint32_t)(grp_)) ^ ((uint32_t)(row_)&7u))<<4))

template<int EPI, int NT>
__global__ __launch_bounds__(256,2) void gemm_h2(
    const __half* __restrict__ Ah, const __half* __restrict__ Al,
    const __half* __restrict__ Bh,
    const float* __restrict__ cosb, const float* __restrict__ sinb,
    const float* __restrict__ bias, float* __restrict__ Out)
{
    extern __shared__ char sm[];
    const uint32_t smb = smem_u32(sm);
    constexpr int STG_B  = (NT+1)*TILE16K;     // 32KB or 48KB
    constexpr int DEPTH  = (NT==1) ? 3 : 2;
    constexpr uint32_t BOFF = (uint32_t)NT*TILE16K;

    const int tid  = threadIdx.x;
    const int wid  = tid >> 5;
    const int lane = tid & 31;
    const int m0 = blockIdx.y * 128;
    const int n0 = blockIdx.x * 128;
    const int wm = wid & 3;
    const int wn = wid >> 2;

    float acc[2][8][4];
#pragma unroll
    for (int im=0;im<2;im++)
#pragma unroll
        for (int j=0;j<8;j++)
#pragma unroll
            for (int q=0;q<4;q++) acc[im][j][q] = 0.f;

#define GISSUE(s_, b_) do{ \
    const uint32_t bb_ = smb + (uint32_t)(b_)*STG_B; \
    const int kt_ = (s_)*KS2; \
    _Pragma("unroll") \
    for (int r_ = 0; r_ < 4; r_++){ \
        const int idx_ = tid + r_*256; \
        const uint32_t row_ = (uint32_t)(idx_ >> 3); \
        const uint32_t grp_ = (uint32_t)(idx_ & 7); \
        const uint32_t dst_ = bb_ + SWZ128(row_, grp_); \
        const uint32_t an_  = ((int)(m0 + row_) < Mn) ? 16u : 0u; \
        const size_t aoff_ = (size_t)(m0 + row_)*Cn + kt_ + grp_*8; \
        const size_t boff_ = (size_t)(n0 + row_)*Cn + kt_ + grp_*8; \
        cpa(dst_, Ah + aoff_, an_); \
        if (NT == 2) cpa(dst_ + TILE16K, Al + aoff_, an_); \
        cpa(dst_ + BOFF, Bh + boff_, 16u); \
    } \
    asm volatile("cp.async.commit_group;":::"memory"); \
}while(0)

    GISSUE(0, 0);
    GISSUE(1, 1);
    if (DEPTH == 3) GISSUE(2, 2);

    const uint32_t ar0 = (uint32_t)(wm*32 + (lane & 15));
    const uint32_t ar1 = ar0 + 16;
    const uint32_t brb = (uint32_t)(wn*64 + (lane & 7) + ((lane >> 4) << 3));

    for (int s = 0; s < NSTG2; s++){
        if (s + 2 < NSTG2 && DEPTH == 3)
            asm volatile("cp.async.wait_group 2;":::"memory");
        else if (s + 1 < NSTG2)
            asm volatile("cp.async.wait_group 1;":::"memory");
        else
            asm volatile("cp.async.wait_group 0;":::"memory");
        __syncthreads();

        const uint32_t sb = smb + (uint32_t)(s % DEPTH)*STG_B;
#pragma unroll
        for (int kk = 0; kk < 4; kk++){
            const uint32_t gA = (uint32_t)(kk*2 + (lane >> 4));
            const uint32_t gB = (uint32_t)(kk*2 + ((lane >> 3) & 1));
            uint32_t ah[2][4], al[2][4], bhf[4][4];
            ldsm4(ah[0], sb + SWZ128(ar0, gA));
            ldsm4(ah[1], sb + SWZ128(ar1, gA));
            if (NT == 2){
                ldsm4(al[0], sb + TILE16K + SWZ128(ar0, gA));
                ldsm4(al[1], sb + TILE16K + SWZ128(ar1, gA));
            }
#pragma unroll
            for (int t2 = 0; t2 < 4; t2++){
                const uint32_t br = brb + (uint32_t)(t2*16);
                ldsm4(bhf[t2], sb + BOFF + SWZ128(br, gB));
            }
#pragma unroll
            for (int im = 0; im < 2; im++)
#pragma unroll
                for (int j = 0; j < 8; j++)
                    mma16816h(acc[im][j], ah[im],
                              bhf[j>>1][(j&1)*2], bhf[j>>1][(j&1)*2+1]);
            if (NT == 2){
#pragma unroll
                for (int im = 0; im < 2; im++)
#pragma unroll
                    for (int j = 0; j < 8; j++)
                        mma16816h(acc[im][j], al[im],
                                  bhf[j>>1][(j&1)*2], bhf[j>>1][(j&1)*2+1]);
            }
        }
        __syncthreads();
        if (s + DEPTH < NSTG2) GISSUE(s + DEPTH, s % DEPTH);
    }
#undef GISSUE

    if (EPI == 0){
        const float QSCALE = 0.125f * 1.44269504088896f;
        int bb4[2][2], n4[2][2];
#pragma unroll
        for (int im = 0; im < 2; im++)
#pragma unroll
            for (int rr = 0; rr < 2; rr++){
                const int m = m0 + wm*32 + im*16 + (lane>>2) + rr*8;
                const int bb = (m < Mn) ? (m / Nn) : 0;
                bb4[im][rr] = bb;
                n4[im][rr]  = m - bb*Nn;
            }
#pragma unroll
        for (int im = 0; im < 2; im++){
#pragma unroll
            for (int j = 0; j < 8; j++){
                const int cl = wn*64 + j*8 + (lane&3)*2;
                const int gc  = n0 + cl;
                const int sec = gc / Cn;
                const int rem = gc - sec*Cn;
                const int hh  = rem >> 6;
                const int d   = rem & 63;
#pragma unroll
                for (int rr = 0; rr < 2; rr++){
                    const int m = m0 + wm*32 + im*16 + (lane>>2) + rr*8;
                    if (m >= Mn) continue;
                    float v1 = acc[im][j][rr*2+0];
                    float v2 = acc[im][j][rr*2+1];
                    const int bb = bb4[im][rr];
                    const int n  = n4[im][rr];
                    if (sec < 2 && n > 0){
                        const float cs = cosb[(n-1)*(Dn/2) + (d>>1)];
                        const float sn = sinb[(n-1)*(Dn/2) + (d>>1)];
                        const float r1 = v1*cs - v2*sn;
                        const float r2 = v1*sn + v2*cs;
                        v1 = r1; v2 = r2;
                    }
                    if (sec == 0){ v1 *= QSCALE; v2 *= QSCALE; }
                    const size_t idx = ((size_t)(bb*Hn + hh)*Nn + n)*Dn + d;
                    if (sec == 0)      store_pairh(g_qh, g_ql, idx, v1, v2);
                    else if (sec == 1) *reinterpret_cast<uint32_t*>(g_k + idx) = packh(v1, v2);
                    else               *reinterpret_cast<uint32_t*>(g_v + idx) = packh(v1, v2);
                }
            }
        }
    } else {
        float* Ds = (float*)sm;
#pragma unroll
        for (int im = 0; im < 2; im++){
#pragma unroll
            for (int j = 0; j < 8; j++){
                const int cl = wn*64 + j*8 + (lane&3)*2;
#pragma unroll
                for (int rr = 0; rr < 2; rr++){
                    const int r = wm*32 + im*16 + (lane>>2) + rr*8;
                    float v1 = acc[im][j][rr*2+0];
                    float v2 = acc[im][j][rr*2+1];
                    const int gc = n0 + cl;
                    v1 += bias[gc]; v2 += bias[gc+1];
                    Ds[r*132 + cl]   = v1;
                    Ds[r*132 + cl+1] = v2;
                }
            }
        }
        __syncthreads();
        const int row  = tid >> 1;
        const int half = tid & 1;
        const int m = m0 + row;
        if (m < Mn){
            float* dst = Out + (size_t)m*Cn + n0 + half*64;
            const float* src = &Ds[row*132 + half*64];
#pragma unroll
            for (int j = 0; j < 64; j += 4)
                *(float4*)&dst[j] = *(const float4*)&src[j];
        }
    }
}

// ---------------------------------------------------------------------------
// HMMA flash attention (R15 + warp guard for fully-out-of-range q warps)
// ---------------------------------------------------------------------------
#define AT_PITCH 144
#define AT_TILE  (64*AT_PITCH)        // 9216
#define KV_STAGE (2*AT_TILE)          // 18432 : K | V
#define AT_SMEM  (36864 + 3*KV_STAGE) // 92160
#define NTkv ((Nn+63)/64)             // 10

__global__ __launch_bounds__(256,2) void attn_tc()
{
    extern __shared__ char sm[];
    const uint32_t smb = smem_u32(sm);
    const int tid  = threadIdx.x;
    const int wid  = tid >> 5;
    const int lane = tid & 31;
    const int qt   = blockIdx.x;
    const int bh   = blockIdx.y;
    const int bb   = bh / Hn;
    const int h    = bh - bb*Hn;
    const bool wactive = (qt*128 + wid*16) < Nn;

    const __half* Qh = g_qh + (size_t)bh*Nn*Dn;
    const __half* Ql = g_ql + (size_t)bh*Nn*Dn;
    const __half* Kp = g_k  + (size_t)bh*Nn*Dn;
    const __half* Vp = g_v  + (size_t)bh*Nn*Dn;

    {
#pragma unroll
        for (int i = 0; i < 4; i++){
            const int idx = tid + i*256;
            const int r   = idx >> 3;
            const int j   = idx & 7;
            const int gr  = qt*128 + r;
            uint4 vh = make_uint4(0,0,0,0), vl = vh;
            if (gr < Nn){
                vh = *(const uint4*)(Qh + (size_t)gr*Dn + j*8);
                vl = *(const uint4*)(Ql + (size_t)gr*Dn + j*8);
            }
            *(uint4*)(sm + r*AT_PITCH + j*16)         = vh;
            *(uint4*)(sm + 18432 + r*AT_PITCH + j*16) = vl;
        }
    }

#define ISSUE_KV(t_, buf_) do{ \
    const int kv0 = (t_)*64; \
    const uint32_t bp = smb + 36864u + (uint32_t)(buf_)*KV_STAGE; \
    _Pragma("unroll") \
    for (int i_ = 0; i_ < 4; i_++){ \
        const int idx = tid + i_*256; \
        const int ts  = idx >> 9; \
        const int rem = idx & 511; \
        const int r_  = rem >> 3; \
        const int j_  = rem & 7; \
        const int gr  = kv0 + r_; \
        const __half* src = ts ? Vp : Kp; \
        const uint32_t n_ = (gr < Nn) ? 16u : 0u; \
        cpa(bp + (uint32_t)ts*AT_TILE + (uint32_t)(r_*AT_PITCH + j_*16), \
            src + (size_t)gr*Dn + j_*8, n_); \
    } \
    asm volatile("cp.async.commit_group;":::"memory"); \
}while(0)

    ISSUE_KV(0, 0);
    ISSUE_KV(1, 1);

    __syncthreads();
    uint32_t qfh[4][4], qfl[4][4];
    if (wactive){
        const uint32_t qa = smb + (uint32_t)((wid*16 + (lane&15))*AT_PITCH + (lane>>4)*16);
#pragma unroll
        for (int kk = 0; kk < 4; kk++){
            ldsm4(qfh[kk], qa + kk*32);
            ldsm4(qfl[kk], qa + 18432 + kk*32);
        }
    }

    float m0r = -1e30f, m1r = -1e30f, l0r = 0.f, l1r = 0.f;
    float o[8][4];
#pragma unroll
    for (int j=0;j<8;j++)
#pragma unroll
        for (int q=0;q<4;q++) o[j][q] = 0.f;

    int buf = 0;
    for (int t = 0; t < NTkv; t++){
        if (t < NTkv-1) asm volatile("cp.async.wait_group 1;":::"memory");
        else            asm volatile("cp.async.wait_group 0;":::"memory");
        __syncthreads();

        const uint32_t sb = smb + 36864u + (uint32_t)buf*KV_STAGE;

        if (wactive){
            float s[8][4];
#pragma unroll
            for (int j=0;j<8;j++)
#pragma unroll
                for (int q=0;q<4;q++) s[j][q] = 0.f;

#pragma unroll
            for (int kk = 0; kk < 4; kk++){
                uint32_t kh[4][4];
#pragma unroll
                for (int g = 0; g < 4; g++){
                    const uint32_t ka = sb
                        + (uint32_t)((g*16 + (lane&7) + ((lane>>4)<<3))*AT_PITCH
                                     + ((lane>>3)&1)*16 + kk*32);
                    ldsm4(kh[g], ka);
                }
#pragma unroll
                for (int j = 0; j < 8; j++)
                    mma16816h(s[j], qfh[kk], kh[j>>1][(j&1)*2], kh[j>>1][(j&1)*2+1]);
#pragma unroll
                for (int j = 0; j < 8; j++)
                    mma16816h(s[j], qfl[kk], kh[j>>1][(j&1)*2], kh[j>>1][(j&1)*2+1]);
            }

            if (t == NTkv-1){
#pragma unroll
                for (int j = 0; j < 8; j++){
                    const int c0 = t*64 + j*8 + (lane&3)*2;
                    if (c0   >= Nn){ s[j][0] = -1e30f; s[j][2] = -1e30f; }
                    if (c0+1 >= Nn){ s[j][1] = -1e30f; s[j][3] = -1e30f; }
                }
            }
            float mx0 = -1e30f, mx1 = -1e30f;
#pragma unroll
            for (int j = 0; j < 8; j++){
                mx0 = fmaxf(mx0, fmaxf(s[j][0], s[j][1]));
                mx1 = fmaxf(mx1, fmaxf(s[j][2], s[j][3]));
            }
            mx0 = fmaxf(mx0, __shfl_xor_sync(0xffffffffu, mx0, 1));
            mx0 = fmaxf(mx0, __shfl_xor_sync(0xffffffffu, mx0, 2));
            mx1 = fmaxf(mx1, __shfl_xor_sync(0xffffffffu, mx1, 1));
            mx1 = fmaxf(mx1, __shfl_xor_sync(0xffffffffu, mx1, 2));
            const float mn0 = fmaxf(m0r, mx0), mn1 = fmaxf(m1r, mx1);
            const float al0 = exp2f(m0r - mn0), al1 = exp2f(m1r - mn1);
            float rs0 = 0.f, rs1 = 0.f;
#pragma unroll
            for (int j = 0; j < 8; j++){
                s[j][0] = exp2f(s[j][0]-mn0); s[j][1] = exp2f(s[j][1]-mn0);
                s[j][2] = exp2f(s[j][2]-mn1); s[j][3] = exp2f(s[j][3]-mn1);
                rs0 += s[j][0] + s[j][1];
                rs1 += s[j][2] + s[j][3];
            }
            rs0 += __shfl_xor_sync(0xffffffffu, rs0, 1);
            rs0 += __shfl_xor_sync(0xffffffffu, rs0, 2);
            rs1 += __shfl_xor_sync(0xffffffffu, rs1, 1);
            rs1 += __shfl_xor_sync(0xffffffffu, rs1, 2);
            l0r = l0r*al0 + rs0;  m0r = mn0;
            l1r = l1r*al1 + rs1;  m1r = mn1;
#pragma unroll
            for (int j = 0; j < 8; j++){
                o[j][0] *= al0; o[j][1] *= al0;
                o[j][2] *= al1; o[j][3] *= al1;
            }

#pragma unroll
            for (int kk = 0; kk < 4; kk++){
                uint32_t pha[4];
                {
                    const int j0 = 2*kk, j1 = 2*kk+1;
                    pha[0] = packh(s[j0][0], s[j0][1]);
                    pha[1] = packh(s[j0][2], s[j0][3]);
                    pha[2] = packh(s[j1][0], s[j1][1]);
                    pha[3] = packh(s[j1][2], s[j1][3]);
                }
                uint32_t vh[4][4];
#pragma unroll
                for (int g = 0; g < 4; g++){
                    const uint32_t va = sb + AT_TILE
                        + (uint32_t)((kk*16 + (lane&7) + ((lane>>3)&1)*8)*AT_PITCH
                                     + ((lane>>4)*8 + g*16)*2);
                    ldsm4t(vh[g], va);
                }
#pragma unroll
                for (int j = 0; j < 8; j++)
                    mma16816h(o[j], pha, vh[j>>1][(j&1)*2], vh[j>>1][(j&1)*2+1]);
            }
        }

        if (t+2 < NTkv){
            const int nb = (t+2) % 3;
            ISSUE_KV(t+2, nb);
        }
        buf = (buf + 1 == 3) ? 0 : buf + 1;
    }
#undef ISSUE_KV

    if (wactive){
        const float inv0 = 1.f / l0r, inv1 = 1.f / l1r;
        const int r0 = qt*128 + wid*16 + (lane>>2);
        const int r1 = r0 + 8;
#pragma unroll
        for (int j = 0; j < 8; j++){
            const int col = h*Dn + j*8 + (lane&3)*2;
            if (r0 < Nn)
                *reinterpret_cast<uint32_t*>(g_aoh + (size_t)(bb*Nn + r0)*Cn + col)
                    = packh(o[j][0]*inv0, o[j][1]*inv0);
            if (r1 < Nn)
                *reinterpret_cast<uint32_t*>(g_aoh + (size_t)(bb*Nn + r1)*Cn + col)
                    = packh(o[j][2]*inv1, o[j][3]*inv1);
        }
    }
}

// ---------------------------------------------------------------------------
extern "C" void kernel_launch(void* const* d_in, const int* in_sizes, int n_in,
                              void* d_out, int out_size)
{
    (void)in_sizes; (void)n_in; (void)out_size;
    const float* x      = (const float*)d_in[0];
    const float* w_qkv  = (const float*)d_in[1];
    const float* w_proj = (const float*)d_in[2];
    const float* b_proj = (const float*)d_in[3];
    const float* cosb   = (const float*)d_in[4];
    const float* sinb   = (const float*)d_in[5];
    float* out = (float*)d_out;

    cudaFuncSetAttribute((const void*)gemm_h2<0,1>,
                         cudaFuncAttributeMaxDynamicSharedMemorySize, SMEM_GM);
    cudaFuncSetAttribute((const void*)gemm_h2<1,1>,
                         cudaFuncAttributeMaxDynamicSharedMemorySize, SMEM_GM);
    cudaFuncSetAttribute(attn_tc, cudaFuncAttributeMaxDynamicSharedMemorySize, AT_SMEM);

    __half *xh, *wq, *wp, *aoh;
    cudaGetSymbolAddress((void**)&xh,  g_xh);
    cudaGetSymbolAddress((void**)&wq,  g_wq);  cudaGetSymbolAddress((void**)&wp,  g_wp);
    cudaGetSymbolAddress((void**)&aoh, g_aoh);

    conv_all<<<NBX + NBQ + NBP, 256>>>(x, w_qkv, w_proj, xh, wq, wp);

    const int MT = (Mn + 127) / 128;   // 145
    gemm_h2<0,1><<<dim3(QKV_N/128, MT), 256, SMEM_GM>>>(xh, nullptr, wq,
                                                        cosb, sinb, nullptr, nullptr);
    attn_tc<<<dim3((Nn+127)/128, Bn*Hn), 256, AT_SMEM>>>();
    gemm_h2<1,1><<<dim3(Cn/128, MT), 256, SMEM_GM>>>(aoh, nullptr, wp,
                                                     nullptr, nullptr, b_proj, out);
}